// round 13
// baseline (speedup 1.0000x reference)
#include <cuda_runtime.h>
#include <math.h>

#define D     32
#define GMAX  64
#define NMAX  100000
#define EMAX  1600000
#define TILE  1024
#define NBMAX ((NMAX + TILE - 1) / TILE)   // 98
#define WPAD  36                           // padded row stride (floats), 144B = 16B-aligned
#define NPW   16                           // nodes per warp (sequential)

// -------- device scratch: referenced ONLY from device code --------
__device__ __align__(16) float g_agg[NMAX * D];    // aggregation result (overwritten per layer)
__device__ __align__(16) float g_x1[NMAX * D];     // layer-1 node features
__device__ unsigned g_max[3 * GMAX * D];           // per-layer segment-max (encoded)
__device__ float    g_Wt[5 * D * D];               // BN-folded TRANSPOSED: Wt[m][col][k]
__device__ float    g_bf[5 * D];
__device__ int      g_deg[NMAX];                   // in-degree histogram
__device__ int      g_off[NMAX + 1];               // CSR row offsets (by dst)
__device__ int      g_cur[NMAX];                   // fill cursors
__device__ int      g_csr[EMAX];                   // src ids grouped by dst
__device__ int      g_bsum[NBMAX];                 // per-tile sums

// monotone float <-> uint mapping so atomicMax(unsigned) == float max
__device__ __forceinline__ unsigned fenc(float f) {
    unsigned u = __float_as_uint(f);
    return (u & 0x80000000u) ? ~u : (u | 0x80000000u);
}
__device__ __forceinline__ float fdec(unsigned k) {
    return __uint_as_float((k & 0x80000000u) ? (k ^ 0x80000000u) : ~k);
}
__device__ __forceinline__ float elu1(float h) { return h > 0.f ? h : expm1f(h); }

// packed f32x2 FMA (sm_100+): acc = a*b + acc, two fp32 lanes per instruction
__device__ __forceinline__ unsigned long long fma2(unsigned long long acc,
                                                   unsigned long long a,
                                                   unsigned long long b) {
    asm("fma.rn.f32x2 %0, %1, %2, %0;" : "+l"(acc) : "l"(a), "l"(b));
    return acc;
}
__device__ __forceinline__ float f2lo(unsigned long long v) {
    return __uint_as_float((unsigned)v);
}
__device__ __forceinline__ float f2hi(unsigned long long v) {
    return __uint_as_float((unsigned)(v >> 32));
}

// -------- prep: fold BN into TRANSPOSED W,b ; init max buffers ; zero histogram --------
__global__ void prep_kernel(const float* __restrict__ linW,  const float* __restrict__ linb,
                            const float* __restrict__ ling,  const float* __restrict__ linbe,
                            const float* __restrict__ linm,  const float* __restrict__ linv,
                            const float* __restrict__ convW, const float* __restrict__ convb,
                            const float* __restrict__ convg, const float* __restrict__ convbe,
                            const float* __restrict__ convm, const float* __restrict__ convv,
                            int N) {
    int t = blockIdx.x * blockDim.x + threadIdx.x;

    if (t < D * D) {
        int col = t >> 5, k = t & 31;      // g_Wt index t = col*D + k
        #pragma unroll
        for (int m = 0; m < 5; m++) {
            const float *W, *b, *g, *be, *mu, *va;
            if (m < 3) {
                W = linW + m*D*D;  b = linb + m*D;  g = ling + m*D;
                be = linbe + m*D;  mu = linm + m*D; va = linv + m*D;
            } else {
                int l = m - 3;
                W = convW + l*D*D; b = convb + l*D; g = convg + l*D;
                be = convbe + l*D; mu = convm + l*D; va = convv + l*D;
            }
            float sc = g[col] * rsqrtf(va[col] + 1e-5f);
            g_Wt[m*D*D + t] = W[k*D + col] * sc;       // transposed + folded
            if (t < D) g_bf[m*D + t] = (b[t] - mu[t]) * sc + be[t];
        }
    }
    if (t < 3*GMAX*D) g_max[t] = 0x007FFFFFu;   // encode(-inf)
    if (t < N) g_deg[t] = 0;
}

// -------- CSR build 1: histogram of dst --------
__global__ void hist_kernel(const int* __restrict__ ei, int E) {
    int e = blockIdx.x * blockDim.x + threadIdx.x;
    if (e < E) atomicAdd(&g_deg[ei[E + e]], 1);
}

// -------- CSR build 2a: per-tile sums (coalesced) --------
__global__ void tilesum_kernel(int N) {
    __shared__ int sm[256];
    int b = blockIdx.x, t = threadIdx.x;
    int base = b * TILE;
    int s = 0;
    for (int i = t; i < TILE; i += 256) {
        int idx = base + i;
        if (idx < N) s += g_deg[idx];
    }
    sm[t] = s;
    __syncthreads();
    for (int o = 128; o > 0; o >>= 1) {
        if (t < o) sm[t] += sm[t + o];
        __syncthreads();
    }
    if (t == 0) g_bsum[b] = sm[0];
}

// -------- CSR build 2b: per-tile scan + self-computed prefix of tile sums --------
__global__ void tileoff_kernel(int N, int E, int NB) {
    __shared__ int sm[TILE];
    __shared__ int red[128];
    __shared__ int sprefix;
    int b = blockIdx.x, t = threadIdx.x;

    if (t < 128) red[t] = (t < b && t < NB) ? g_bsum[t] : 0;
    __syncthreads();
    if (t < 64) red[t] += red[t + 64];
    __syncthreads();
    if (t < 32) {
        int v = red[t] + red[t + 32];
        #pragma unroll
        for (int o = 16; o > 0; o >>= 1) v += __shfl_down_sync(0xffffffffu, v, o);
        if (t == 0) sprefix = v;
    }

    int idx = b * TILE + t;
    int v = (idx < N) ? g_deg[idx] : 0;
    sm[t] = v;
    __syncthreads();
    for (int o = 1; o < TILE; o <<= 1) {
        int y = (t >= o) ? sm[t - o] : 0;
        __syncthreads();
        sm[t] += y;
        __syncthreads();
    }
    if (idx < N) {
        int excl = sprefix + sm[t] - v;
        g_off[idx] = excl;
        g_cur[idx] = excl;
        if (idx == N - 1) g_off[N] = E;
    }
}

// -------- CSR build 3: fill src ids grouped by dst --------
__global__ void fill_kernel(const int* __restrict__ ei, int E) {
    int e = blockIdx.x * blockDim.x + threadIdx.x;
    if (e >= E) return;
    int s = ei[e];
    int d = ei[E + e];
    int pos = atomicAdd(&g_cur[d], 1);
    g_csr[pos] = s;
}

// -------- aggregation via CSR gather: g_agg[node] = sum_{s in row(node)} x[s] --------
template <int L>
__global__ void __launch_bounds__(256)
agg_kernel(const float* __restrict__ xarg, int N) {
    const float* __restrict__ x = (L == 0) ? xarg : g_x1;
    int t = threadIdx.x;
    int node = (blockIdx.x * 256 + t) >> 5;
    int lane = t & 31;
    if (node >= N) return;

    int rs = __ldg(&g_off[node]), re = __ldg(&g_off[node + 1]);
    float acc = 0.f;
    int k = rs;
    for (; k + 8 <= re; k += 8) {
        int i0 = __ldg(&g_csr[k]),     i1 = __ldg(&g_csr[k + 1]);
        int i2 = __ldg(&g_csr[k + 2]), i3 = __ldg(&g_csr[k + 3]);
        int i4 = __ldg(&g_csr[k + 4]), i5 = __ldg(&g_csr[k + 5]);
        int i6 = __ldg(&g_csr[k + 6]), i7 = __ldg(&g_csr[k + 7]);
        float v0 = __ldg(&x[i0*D + lane]), v1 = __ldg(&x[i1*D + lane]);
        float v2 = __ldg(&x[i2*D + lane]), v3 = __ldg(&x[i3*D + lane]);
        float v4 = __ldg(&x[i4*D + lane]), v5 = __ldg(&x[i5*D + lane]);
        float v6 = __ldg(&x[i6*D + lane]), v7 = __ldg(&x[i7*D + lane]);
        acc += ((v0 + v1) + (v2 + v3)) + ((v4 + v5) + (v6 + v7));
    }
    for (; k < re; k++) acc += __ldg(&x[__ldg(&g_csr[k])*D + lane]);
    g_agg[node*D + lane] = acc;
}

// Dot-product GEMM with packed f32x2 FMA (FFMA2):
//   h[lane] = B[lane] + sum_k x[k] * Wt[lane][k]
// 8×(2 LDS.128 + 2 FFMA2) per lane, two independent packed accumulators.
#define DOT32(H, SROW, WT, B)                                               \
    {                                                                       \
        unsigned long long a0 = 0ull, a1 = 0ull;                            \
        _Pragma("unroll")                                                   \
        for (int k4 = 0; k4 < 8; k4++) {                                    \
            ulonglong2 xv = *(const ulonglong2*)&(SROW)[k4 * 4];            \
            ulonglong2 wv = *(const ulonglong2*)&(WT)[lane * WPAD + k4*4];  \
            a0 = fma2(a0, xv.x, wv.x);                                      \
            a1 = fma2(a1, xv.y, wv.y);                                      \
        }                                                                   \
        H = (B)[lane] + ((f2lo(a0) + f2lo(a1)) + (f2hi(a0) + f2hi(a1)));    \
    }

// -------- fused GIN layer: warp processes NPW consecutive nodes --------
// Weights amortized over 8*NPW nodes/block; segment-max kept in registers and
// flushed once per warp-batch (batch[] is sorted, so seg changes are rare).
template <bool FIRST>
__global__ void __launch_bounds__(256)
fused_kernel(const float* __restrict__ xarg, float* __restrict__ xoutarg,
             const int* __restrict__ batch, const float* __restrict__ lw,
             float* __restrict__ Zbuf, int N) {
    constexpr int cm = FIRST ? 3 : 4;   // conv weight slot
    constexpr int lm = FIRST ? 1 : 2;   // lin weight slot
    __shared__ __align__(16) float Wc[D*WPAD];
    __shared__ __align__(16) float Wl[D*WPAD];
    __shared__ __align__(16) float W0[FIRST ? D*WPAD : 4];
    __shared__ float bc[D], bl[D], b0[FIRST ? D : 1];
    __shared__ __align__(16) float sSt[8][WPAD];    // per-warp staged input vector

    int t = threadIdx.x;
    for (int i = t; i < D*D; i += 256) {
        int col = i >> 5, k = i & 31;
        Wc[col*WPAD + k] = g_Wt[cm*D*D + i];
        Wl[col*WPAD + k] = g_Wt[lm*D*D + i];
        if (FIRST) W0[col*WPAD + k] = g_Wt[i];
    }
    if (t < D) {
        bc[t] = g_bf[cm*D + t];
        bl[t] = g_bf[lm*D + t];
        if (FIRST) b0[t] = g_bf[t];
    }
    __syncthreads();

    int w = t >> 5, lane = t & 31;
    int n0 = (blockIdx.x * 8 + w) * NPW;
    if (n0 >= N) return;
    int nend = n0 + NPW; if (nend > N) nend = N;

    const float* xin  = FIRST ? xarg : g_x1;
    float*       xout = FIRST ? g_x1 : xoutarg;
    float lw0 = FIRST ? lw[0] : 0.f;
    float lwl = lw[FIRST ? 1 : 2];

    const float NEGINF = __uint_as_float(0xff800000u);
    float z0max = NEGINF, z1max = NEGINF;
    int curseg = batch[n0];

    for (int node = n0; node < nend; node++) {
        int seg = batch[node];
        if (seg != curseg) {               // rare (batch sorted): flush maxes
            if (FIRST) atomicMax(&g_max[curseg*D + lane], fenc(z0max));
            atomicMax(&g_max[(FIRST ? 1 : 2)*GMAX*D + curseg*D + lane], fenc(z1max));
            z0max = NEGINF; z1max = NEGINF;
            curseg = seg;
        }

        float xself = xin[(size_t)node*D + lane];
        float acc = xself + g_agg[(size_t)node*D + lane];

        // ---- optional layer-0 lin-MLP on raw x ----
        float Zval = 0.f;
        if (FIRST) {
            sSt[w][lane] = xself;
            __syncwarp();
            float h0;
            DOT32(h0, sSt[w], W0, b0);
            float z0 = elu1(h0);
            Zval = lw0 * z0;
            z0max = fmaxf(z0max, z0);      // layer0 max over RAW z0
            __syncwarp();
        }

        // ---- conv MLP: x' = ELU(BNfold(acc @ Wc)) ----
        sSt[w][lane] = acc;
        __syncwarp();
        float h1;
        DOT32(h1, sSt[w], Wc, bc);
        float xn = elu1(h1);
        xout[(size_t)node*D + lane] = xn;
        __syncwarp();

        // ---- lin MLP: z = lw * ELU(BNfold(x' @ Wl)) ----
        sSt[w][lane] = xn;
        __syncwarp();
        float h2;
        DOT32(h2, sSt[w], Wl, bl);
        float z = lwl * elu1(h2);

        if (FIRST) Zbuf[(size_t)node*D + lane] = Zval + z;
        else       Zbuf[(size_t)node*D + lane] += z;
        z1max = fmaxf(z1max, z);
    }

    // final flush (fenc(-inf) == init value, so this is always safe)
    if (FIRST) atomicMax(&g_max[curseg*D + lane], fenc(z0max));
    atomicMax(&g_max[(FIRST ? 1 : 2)*GMAX*D + curseg*D + lane], fenc(z1max));
}

// -------- out = sum of the three per-layer segment maxes --------
__global__ void final_kernel(float* __restrict__ out) {
    int i = blockIdx.x * blockDim.x + threadIdx.x;
    if (i < GMAX*D)
        out[i] = fdec(g_max[i]) + fdec(g_max[GMAX*D + i]) + fdec(g_max[2*GMAX*D + i]);
}

extern "C" void kernel_launch(void* const* d_in, const int* in_sizes, int n_in,
                              void* d_out, int out_size) {
    const float* x      = (const float*)d_in[0];
    const int*   ei     = (const int*)d_in[1];      // int32 (JAX x64 disabled)
    const int*   batch  = (const int*)d_in[2];
    const float* lw     = (const float*)d_in[3];
    const float* linW   = (const float*)d_in[4];
    const float* linb   = (const float*)d_in[5];
    const float* ling   = (const float*)d_in[6];
    const float* linbe  = (const float*)d_in[7];
    const float* linm   = (const float*)d_in[8];
    const float* linv   = (const float*)d_in[9];
    const float* convW  = (const float*)d_in[10];
    const float* convb  = (const float*)d_in[11];
    const float* convg  = (const float*)d_in[12];
    const float* convbe = (const float*)d_in[13];
    const float* convm  = (const float*)d_in[14];
    const float* convv  = (const float*)d_in[15];

    int N = in_sizes[0] / D;
    int E = in_sizes[1] / 2;
    int NB = (N + TILE - 1) / TILE;

    float* out = (float*)d_out;            // [G*D]
    float* Z   = out + GMAX * D;           // [N*D]
    float* xb  = Z + (size_t)N * D;        // [N*D] final x output

    int aggw_blocks  = (N * 32 + 255) / 256;            // warp-per-node (agg)
    int fused_blocks = (N + 8*NPW - 1) / (8*NPW);       // 128 nodes per block
    int e_blocks = (E + 255) / 256;
    int prep_n = N > 5*D*D ? N : 5*D*D;

    prep_kernel<<<(prep_n + 1023) / 1024, 1024>>>(linW, linb, ling, linbe, linm, linv,
                                                  convW, convb, convg, convbe, convm, convv, N);

    // CSR build (shared by both layers)
    hist_kernel<<<e_blocks, 256>>>(ei, E);
    tilesum_kernel<<<NB, 256>>>(N);
    tileoff_kernel<<<NB, TILE>>>(N, E, NB);
    fill_kernel<<<e_blocks, 256>>>(ei, E);

    // layer 1: gather-agg(x) -> g_agg; fused l0 + conv0 + lin1 (x -> g_x1)
    agg_kernel<0><<<aggw_blocks, 256>>>(x, N);
    fused_kernel<true><<<fused_blocks, 256>>>(x, nullptr, batch, lw, Z, N);

    // layer 2: gather-agg(g_x1) -> g_agg; fused conv1 + lin2 (g_x1 -> xb)
    agg_kernel<1><<<aggw_blocks, 256>>>(nullptr, N);
    fused_kernel<false><<<fused_blocks, 256>>>(nullptr, xb, batch, lw, Z, N);

    final_kernel<<<(GMAX*D + 255) / 256, 256>>>(out);
}

// round 14
// speedup vs baseline: 1.0658x; 1.0658x over previous
#include <cuda_runtime.h>
#include <math.h>

#define D     32
#define GMAX  64
#define NMAX  100000
#define EMAX  1600000
#define TILE  1024
#define NBMAX ((NMAX + TILE - 1) / TILE)   // 98
#define WPAD  36                           // padded row stride (floats), 144B = 16B-aligned
#define NPW   8                            // nodes per warp (sequential)

// -------- device scratch: referenced ONLY from device code --------
__device__ __align__(16) float g_agg[NMAX * D];    // aggregation result (overwritten per layer)
__device__ __align__(16) float g_x1[NMAX * D];     // layer-1 node features
__device__ unsigned g_max[3 * GMAX * D];           // per-layer segment-max (encoded)
__device__ float    g_Wt[5 * D * D];               // BN-folded TRANSPOSED: Wt[m][col][k]
__device__ float    g_bf[5 * D];
__device__ int      g_deg[NMAX];                   // in-degree histogram
__device__ int      g_off[NMAX + 1];               // CSR row offsets (by dst)
__device__ int      g_cur[NMAX];                   // fill cursors
__device__ int      g_csr[EMAX];                   // src ids grouped by dst
__device__ int      g_bsum[NBMAX];                 // per-tile sums

// monotone float <-> uint mapping so atomicMax(unsigned) == float max
__device__ __forceinline__ unsigned fenc(float f) {
    unsigned u = __float_as_uint(f);
    return (u & 0x80000000u) ? ~u : (u | 0x80000000u);
}
__device__ __forceinline__ float fdec(unsigned k) {
    return __uint_as_float((k & 0x80000000u) ? (k ^ 0x80000000u) : ~k);
}
__device__ __forceinline__ float elu1(float h) { return h > 0.f ? h : expm1f(h); }

// packed f32x2 FMA (sm_100+): acc = a*b + acc, two fp32 lanes per instruction
__device__ __forceinline__ unsigned long long fma2(unsigned long long acc,
                                                   unsigned long long a,
                                                   unsigned long long b) {
    asm("fma.rn.f32x2 %0, %1, %2, %0;" : "+l"(acc) : "l"(a), "l"(b));
    return acc;
}
__device__ __forceinline__ float f2lo(unsigned long long v) {
    return __uint_as_float((unsigned)v);
}
__device__ __forceinline__ float f2hi(unsigned long long v) {
    return __uint_as_float((unsigned)(v >> 32));
}

// -------- prep: fold BN into TRANSPOSED W,b ; init max buffers ; zero histogram --------
__global__ void prep_kernel(const float* __restrict__ linW,  const float* __restrict__ linb,
                            const float* __restrict__ ling,  const float* __restrict__ linbe,
                            const float* __restrict__ linm,  const float* __restrict__ linv,
                            const float* __restrict__ convW, const float* __restrict__ convb,
                            const float* __restrict__ convg, const float* __restrict__ convbe,
                            const float* __restrict__ convm, const float* __restrict__ convv,
                            int N) {
    int t = blockIdx.x * blockDim.x + threadIdx.x;

    if (t < D * D) {
        int col = t >> 5, k = t & 31;      // g_Wt index t = col*D + k
        #pragma unroll
        for (int m = 0; m < 5; m++) {
            const float *W, *b, *g, *be, *mu, *va;
            if (m < 3) {
                W = linW + m*D*D;  b = linb + m*D;  g = ling + m*D;
                be = linbe + m*D;  mu = linm + m*D; va = linv + m*D;
            } else {
                int l = m - 3;
                W = convW + l*D*D; b = convb + l*D; g = convg + l*D;
                be = convbe + l*D; mu = convm + l*D; va = convv + l*D;
            }
            float sc = g[col] * rsqrtf(va[col] + 1e-5f);
            g_Wt[m*D*D + t] = W[k*D + col] * sc;       // transposed + folded
            if (t < D) g_bf[m*D + t] = (b[t] - mu[t]) * sc + be[t];
        }
    }
    if (t < 3*GMAX*D) g_max[t] = 0x007FFFFFu;   // encode(-inf)
    if (t < N) g_deg[t] = 0;
}

// -------- CSR build 1: histogram of dst --------
__global__ void hist_kernel(const int* __restrict__ ei, int E) {
    int e = blockIdx.x * blockDim.x + threadIdx.x;
    if (e < E) atomicAdd(&g_deg[ei[E + e]], 1);
}

// -------- CSR build 2a: per-tile sums (coalesced) --------
__global__ void tilesum_kernel(int N) {
    __shared__ int sm[256];
    int b = blockIdx.x, t = threadIdx.x;
    int base = b * TILE;
    int s = 0;
    for (int i = t; i < TILE; i += 256) {
        int idx = base + i;
        if (idx < N) s += g_deg[idx];
    }
    sm[t] = s;
    __syncthreads();
    for (int o = 128; o > 0; o >>= 1) {
        if (t < o) sm[t] += sm[t + o];
        __syncthreads();
    }
    if (t == 0) g_bsum[b] = sm[0];
}

// -------- CSR build 2b: per-tile scan + self-computed prefix of tile sums --------
__global__ void tileoff_kernel(int N, int E, int NB) {
    __shared__ int sm[TILE];
    __shared__ int red[128];
    __shared__ int sprefix;
    int b = blockIdx.x, t = threadIdx.x;

    if (t < 128) red[t] = (t < b && t < NB) ? g_bsum[t] : 0;
    __syncthreads();
    if (t < 64) red[t] += red[t + 64];
    __syncthreads();
    if (t < 32) {
        int v = red[t] + red[t + 32];
        #pragma unroll
        for (int o = 16; o > 0; o >>= 1) v += __shfl_down_sync(0xffffffffu, v, o);
        if (t == 0) sprefix = v;
    }

    int idx = b * TILE + t;
    int v = (idx < N) ? g_deg[idx] : 0;
    sm[t] = v;
    __syncthreads();
    for (int o = 1; o < TILE; o <<= 1) {
        int y = (t >= o) ? sm[t - o] : 0;
        __syncthreads();
        sm[t] += y;
        __syncthreads();
    }
    if (idx < N) {
        int excl = sprefix + sm[t] - v;
        g_off[idx] = excl;
        g_cur[idx] = excl;
        if (idx == N - 1) g_off[N] = E;
    }
}

// -------- CSR build 3: fill src ids grouped by dst --------
__global__ void fill_kernel(const int* __restrict__ ei, int E) {
    int e = blockIdx.x * blockDim.x + threadIdx.x;
    if (e >= E) return;
    int s = ei[e];
    int d = ei[E + e];
    int pos = atomicAdd(&g_cur[d], 1);
    g_csr[pos] = s;
}

// -------- aggregation via CSR gather: g_agg[node] = sum_{s in row(node)} x[s] --------
template <int L>
__global__ void __launch_bounds__(256)
agg_kernel(const float* __restrict__ xarg, int N) {
    const float* __restrict__ x = (L == 0) ? xarg : g_x1;
    int t = threadIdx.x;
    int node = (blockIdx.x * 256 + t) >> 5;
    int lane = t & 31;
    if (node >= N) return;

    int rs = __ldg(&g_off[node]), re = __ldg(&g_off[node + 1]);
    float acc = 0.f;
    int k = rs;
    for (; k + 8 <= re; k += 8) {
        int i0 = __ldg(&g_csr[k]),     i1 = __ldg(&g_csr[k + 1]);
        int i2 = __ldg(&g_csr[k + 2]), i3 = __ldg(&g_csr[k + 3]);
        int i4 = __ldg(&g_csr[k + 4]), i5 = __ldg(&g_csr[k + 5]);
        int i6 = __ldg(&g_csr[k + 6]), i7 = __ldg(&g_csr[k + 7]);
        float v0 = __ldg(&x[i0*D + lane]), v1 = __ldg(&x[i1*D + lane]);
        float v2 = __ldg(&x[i2*D + lane]), v3 = __ldg(&x[i3*D + lane]);
        float v4 = __ldg(&x[i4*D + lane]), v5 = __ldg(&x[i5*D + lane]);
        float v6 = __ldg(&x[i6*D + lane]), v7 = __ldg(&x[i7*D + lane]);
        acc += ((v0 + v1) + (v2 + v3)) + ((v4 + v5) + (v6 + v7));
    }
    for (; k < re; k++) acc += __ldg(&x[__ldg(&g_csr[k])*D + lane]);
    g_agg[node*D + lane] = acc;
}

// Dot-product GEMM with packed f32x2 FMA (FFMA2):
//   h[lane] = B[lane] + sum_k x[k] * Wt[lane][k]
// 8×(2 LDS.128 + 2 FFMA2) per lane, two independent packed accumulators.
#define DOT32(H, SROW, WT, B)                                               \
    {                                                                       \
        unsigned long long a0 = 0ull, a1 = 0ull;                            \
        _Pragma("unroll")                                                   \
        for (int k4 = 0; k4 < 8; k4++) {                                    \
            ulonglong2 xv = *(const ulonglong2*)&(SROW)[k4 * 4];            \
            ulonglong2 wv = *(const ulonglong2*)&(WT)[lane * WPAD + k4*4];  \
            a0 = fma2(a0, xv.x, wv.x);                                      \
            a1 = fma2(a1, xv.y, wv.y);                                      \
        }                                                                   \
        H = (B)[lane] + ((f2lo(a0) + f2lo(a1)) + (f2hi(a0) + f2hi(a1)));    \
    }

// -------- fused GIN layer: warp processes NPW consecutive nodes --------
// Weights amortized over 8*NPW nodes/block; segment-max kept in registers and
// flushed once per warp-batch (batch[] is sorted, so seg changes are rare).
template <bool FIRST>
__global__ void __launch_bounds__(256)
fused_kernel(const float* __restrict__ xarg, float* __restrict__ xoutarg,
             const int* __restrict__ batch, const float* __restrict__ lw,
             float* __restrict__ Zbuf, int N) {
    constexpr int cm = FIRST ? 3 : 4;   // conv weight slot
    constexpr int lm = FIRST ? 1 : 2;   // lin weight slot
    __shared__ __align__(16) float Wc[D*WPAD];
    __shared__ __align__(16) float Wl[D*WPAD];
    __shared__ __align__(16) float W0[FIRST ? D*WPAD : 4];
    __shared__ float bc[D], bl[D], b0[FIRST ? D : 1];
    __shared__ __align__(16) float sSt[8][WPAD];    // per-warp staged input vector

    int t = threadIdx.x;
    for (int i = t; i < D*D; i += 256) {
        int col = i >> 5, k = i & 31;
        Wc[col*WPAD + k] = g_Wt[cm*D*D + i];
        Wl[col*WPAD + k] = g_Wt[lm*D*D + i];
        if (FIRST) W0[col*WPAD + k] = g_Wt[i];
    }
    if (t < D) {
        bc[t] = g_bf[cm*D + t];
        bl[t] = g_bf[lm*D + t];
        if (FIRST) b0[t] = g_bf[t];
    }
    __syncthreads();

    int w = t >> 5, lane = t & 31;
    int n0 = (blockIdx.x * 8 + w) * NPW;
    if (n0 >= N) return;
    int nend = n0 + NPW; if (nend > N) nend = N;

    const float* xin  = FIRST ? xarg : g_x1;
    float*       xout = FIRST ? g_x1 : xoutarg;
    float lw0 = FIRST ? lw[0] : 0.f;
    float lwl = lw[FIRST ? 1 : 2];

    const float NEGINF = __uint_as_float(0xff800000u);
    float z0max = NEGINF, z1max = NEGINF;
    int curseg = batch[n0];

    for (int node = n0; node < nend; node++) {
        int seg = batch[node];
        if (seg != curseg) {               // rare (batch sorted): flush maxes
            if (FIRST) atomicMax(&g_max[curseg*D + lane], fenc(z0max));
            atomicMax(&g_max[(FIRST ? 1 : 2)*GMAX*D + curseg*D + lane], fenc(z1max));
            z0max = NEGINF; z1max = NEGINF;
            curseg = seg;
        }

        float xself = xin[(size_t)node*D + lane];
        float acc = xself + g_agg[(size_t)node*D + lane];

        // ---- optional layer-0 lin-MLP on raw x ----
        float Zval = 0.f;
        if (FIRST) {
            sSt[w][lane] = xself;
            __syncwarp();
            float h0;
            DOT32(h0, sSt[w], W0, b0);
            float z0 = elu1(h0);
            Zval = lw0 * z0;
            z0max = fmaxf(z0max, z0);      // layer0 max over RAW z0
            __syncwarp();
        }

        // ---- conv MLP: x' = ELU(BNfold(acc @ Wc)) ----
        sSt[w][lane] = acc;
        __syncwarp();
        float h1;
        DOT32(h1, sSt[w], Wc, bc);
        float xn = elu1(h1);
        xout[(size_t)node*D + lane] = xn;
        __syncwarp();

        // ---- lin MLP: z = lw * ELU(BNfold(x' @ Wl)) ----
        sSt[w][lane] = xn;
        __syncwarp();
        float h2;
        DOT32(h2, sSt[w], Wl, bl);
        float z = lwl * elu1(h2);

        if (FIRST) Zbuf[(size_t)node*D + lane] = Zval + z;
        else       Zbuf[(size_t)node*D + lane] += z;
        z1max = fmaxf(z1max, z);
    }

    // final flush (fenc(-inf) == init value, so this is always safe)
    if (FIRST) atomicMax(&g_max[curseg*D + lane], fenc(z0max));
    atomicMax(&g_max[(FIRST ? 1 : 2)*GMAX*D + curseg*D + lane], fenc(z1max));
}

// -------- out = sum of the three per-layer segment maxes --------
__global__ void final_kernel(float* __restrict__ out) {
    int i = blockIdx.x * blockDim.x + threadIdx.x;
    if (i < GMAX*D)
        out[i] = fdec(g_max[i]) + fdec(g_max[GMAX*D + i]) + fdec(g_max[2*GMAX*D + i]);
}

extern "C" void kernel_launch(void* const* d_in, const int* in_sizes, int n_in,
                              void* d_out, int out_size) {
    const float* x      = (const float*)d_in[0];
    const int*   ei     = (const int*)d_in[1];      // int32 (JAX x64 disabled)
    const int*   batch  = (const int*)d_in[2];
    const float* lw     = (const float*)d_in[3];
    const float* linW   = (const float*)d_in[4];
    const float* linb   = (const float*)d_in[5];
    const float* ling   = (const float*)d_in[6];
    const float* linbe  = (const float*)d_in[7];
    const float* linm   = (const float*)d_in[8];
    const float* linv   = (const float*)d_in[9];
    const float* convW  = (const float*)d_in[10];
    const float* convb  = (const float*)d_in[11];
    const float* convg  = (const float*)d_in[12];
    const float* convbe = (const float*)d_in[13];
    const float* convm  = (const float*)d_in[14];
    const float* convv  = (const float*)d_in[15];

    int N = in_sizes[0] / D;
    int E = in_sizes[1] / 2;
    int NB = (N + TILE - 1) / TILE;

    float* out = (float*)d_out;            // [G*D]
    float* Z   = out + GMAX * D;           // [N*D]
    float* xb  = Z + (size_t)N * D;        // [N*D] final x output

    int aggw_blocks  = (N * 32 + 255) / 256;            // warp-per-node (agg)
    int fused_blocks = (N + 8*NPW - 1) / (8*NPW);       // 64 nodes per block
    int e_blocks = (E + 255) / 256;
    int prep_n = N > 5*D*D ? N : 5*D*D;

    prep_kernel<<<(prep_n + 1023) / 1024, 1024>>>(linW, linb, ling, linbe, linm, linv,
                                                  convW, convb, convg, convbe, convm, convv, N);

    // CSR build (shared by both layers)
    hist_kernel<<<e_blocks, 256>>>(ei, E);
    tilesum_kernel<<<NB, 256>>>(N);
    tileoff_kernel<<<NB, TILE>>>(N, E, NB);
    fill_kernel<<<e_blocks, 256>>>(ei, E);

    // layer 1: gather-agg(x) -> g_agg; fused l0 + conv0 + lin1 (x -> g_x1)
    agg_kernel<0><<<aggw_blocks, 256>>>(x, N);
    fused_kernel<true><<<fused_blocks, 256>>>(x, nullptr, batch, lw, Z, N);

    // layer 2: gather-agg(g_x1) -> g_agg; fused conv1 + lin2 (g_x1 -> xb)
    agg_kernel<1><<<aggw_blocks, 256>>>(nullptr, N);
    fused_kernel<false><<<fused_blocks, 256>>>(nullptr, xb, batch, lw, Z, N);

    final_kernel<<<(GMAX*D + 255) / 256, 256>>>(out);
}

// round 15
// speedup vs baseline: 1.1496x; 1.0787x over previous
#include <cuda_runtime.h>
#include <math.h>

#define D     32
#define GMAX  64
#define NMAX  100000
#define EMAX  1600000
#define TILE  1024
#define NBMAX ((NMAX + TILE - 1) / TILE)   // 98
#define WPAD  36                           // padded row stride (floats), 144B = 16B-aligned
#define NPW   8                            // nodes per warp (sequential)

// -------- device scratch: referenced ONLY from device code --------
__device__ __align__(16) float g_x1[NMAX * D];     // layer-1 node features
__device__ unsigned g_max[3 * GMAX * D];           // per-layer segment-max (encoded)
__device__ float    g_Wt[5 * D * D];               // BN-folded TRANSPOSED: Wt[m][col][k]
__device__ float    g_bf[5 * D];
__device__ int      g_deg[NMAX];                   // in-degree histogram
__device__ int      g_off[NMAX + 1];               // CSR row offsets (by dst)
__device__ int      g_cur[NMAX];                   // fill cursors
__device__ int      g_csr[EMAX];                   // src ids grouped by dst
__device__ int      g_bsum[NBMAX];                 // per-tile sums

// monotone float <-> uint mapping so atomicMax(unsigned) == float max
__device__ __forceinline__ unsigned fenc(float f) {
    unsigned u = __float_as_uint(f);
    return (u & 0x80000000u) ? ~u : (u | 0x80000000u);
}
__device__ __forceinline__ float fdec(unsigned k) {
    return __uint_as_float((k & 0x80000000u) ? (k ^ 0x80000000u) : ~k);
}
__device__ __forceinline__ float elu1(float h) { return h > 0.f ? h : expm1f(h); }

// packed f32x2 FMA (sm_100+): acc = a*b + acc, two fp32 lanes per instruction
__device__ __forceinline__ unsigned long long fma2(unsigned long long acc,
                                                   unsigned long long a,
                                                   unsigned long long b) {
    asm("fma.rn.f32x2 %0, %1, %2, %0;" : "+l"(acc) : "l"(a), "l"(b));
    return acc;
}
__device__ __forceinline__ float f2lo(unsigned long long v) {
    return __uint_as_float((unsigned)v);
}
__device__ __forceinline__ float f2hi(unsigned long long v) {
    return __uint_as_float((unsigned)(v >> 32));
}

// -------- prep: fold BN into TRANSPOSED W,b ; init max buffers ; zero histogram --------
__global__ void prep_kernel(const float* __restrict__ linW,  const float* __restrict__ linb,
                            const float* __restrict__ ling,  const float* __restrict__ linbe,
                            const float* __restrict__ linm,  const float* __restrict__ linv,
                            const float* __restrict__ convW, const float* __restrict__ convb,
                            const float* __restrict__ convg, const float* __restrict__ convbe,
                            const float* __restrict__ convm, const float* __restrict__ convv,
                            int N) {
    int t = blockIdx.x * blockDim.x + threadIdx.x;

    if (t < D * D) {
        int col = t >> 5, k = t & 31;      // g_Wt index t = col*D + k
        #pragma unroll
        for (int m = 0; m < 5; m++) {
            const float *W, *b, *g, *be, *mu, *va;
            if (m < 3) {
                W = linW + m*D*D;  b = linb + m*D;  g = ling + m*D;
                be = linbe + m*D;  mu = linm + m*D; va = linv + m*D;
            } else {
                int l = m - 3;
                W = convW + l*D*D; b = convb + l*D; g = convg + l*D;
                be = convbe + l*D; mu = convm + l*D; va = convv + l*D;
            }
            float sc = g[col] * rsqrtf(va[col] + 1e-5f);
            g_Wt[m*D*D + t] = W[k*D + col] * sc;       // transposed + folded
            if (t < D) g_bf[m*D + t] = (b[t] - mu[t]) * sc + be[t];
        }
    }
    if (t < 3*GMAX*D) g_max[t] = 0x007FFFFFu;   // encode(-inf)
    if (t < N) g_deg[t] = 0;
}

// -------- CSR build 1: histogram of dst --------
__global__ void hist_kernel(const int* __restrict__ ei, int E) {
    int e = blockIdx.x * blockDim.x + threadIdx.x;
    if (e < E) atomicAdd(&g_deg[ei[E + e]], 1);
}

// -------- CSR build 2a: per-tile sums (coalesced) --------
__global__ void tilesum_kernel(int N) {
    __shared__ int sm[256];
    int b = blockIdx.x, t = threadIdx.x;
    int base = b * TILE;
    int s = 0;
    for (int i = t; i < TILE; i += 256) {
        int idx = base + i;
        if (idx < N) s += g_deg[idx];
    }
    sm[t] = s;
    __syncthreads();
    for (int o = 128; o > 0; o >>= 1) {
        if (t < o) sm[t] += sm[t + o];
        __syncthreads();
    }
    if (t == 0) g_bsum[b] = sm[0];
}

// -------- CSR build 2b: per-tile scan + self-computed prefix of tile sums --------
__global__ void tileoff_kernel(int N, int E, int NB) {
    __shared__ int sm[TILE];
    __shared__ int red[128];
    __shared__ int sprefix;
    int b = blockIdx.x, t = threadIdx.x;

    if (t < 128) red[t] = (t < b && t < NB) ? g_bsum[t] : 0;
    __syncthreads();
    if (t < 64) red[t] += red[t + 64];
    __syncthreads();
    if (t < 32) {
        int v = red[t] + red[t + 32];
        #pragma unroll
        for (int o = 16; o > 0; o >>= 1) v += __shfl_down_sync(0xffffffffu, v, o);
        if (t == 0) sprefix = v;
    }

    int idx = b * TILE + t;
    int v = (idx < N) ? g_deg[idx] : 0;
    sm[t] = v;
    __syncthreads();
    for (int o = 1; o < TILE; o <<= 1) {
        int y = (t >= o) ? sm[t - o] : 0;
        __syncthreads();
        sm[t] += y;
        __syncthreads();
    }
    if (idx < N) {
        int excl = sprefix + sm[t] - v;
        g_off[idx] = excl;
        g_cur[idx] = excl;
        if (idx == N - 1) g_off[N] = E;
    }
}

// -------- CSR build 3: fill src ids grouped by dst --------
__global__ void fill_kernel(const int* __restrict__ ei, int E) {
    int e = blockIdx.x * blockDim.x + threadIdx.x;
    if (e >= E) return;
    int s = ei[e];
    int d = ei[E + e];
    int pos = atomicAdd(&g_cur[d], 1);
    g_csr[pos] = s;
}

// Dot-product GEMM with packed f32x2 FMA (FFMA2):
//   h[lane] = B[lane] + sum_k x[k] * Wt[lane][k]
#define DOT32(H, SROW, WT, B)                                               \
    {                                                                       \
        unsigned long long a0 = 0ull, a1 = 0ull;                            \
        _Pragma("unroll")                                                   \
        for (int k4 = 0; k4 < 8; k4++) {                                    \
            ulonglong2 xv = *(const ulonglong2*)&(SROW)[k4 * 4];            \
            ulonglong2 wv = *(const ulonglong2*)&(WT)[lane * WPAD + k4*4];  \
            a0 = fma2(a0, xv.x, wv.x);                                      \
            a1 = fma2(a1, xv.y, wv.y);                                      \
        }                                                                   \
        H = (B)[lane] + ((f2lo(a0) + f2lo(a1)) + (f2hi(a0) + f2hi(a1)));    \
    }

// -------- fused GIN layer with INLINE gather: warp processes NPW nodes --------
// Per node: acc = x[node] + sum_{s in CSR row} x[s]  (gather, no g_agg round-trip),
// then conv-MLP + lin-MLP (+ lin0 if FIRST). Weights amortized over 8*NPW nodes;
// segment-max registered per warp-batch (batch[] sorted).
template <bool FIRST>
__global__ void __launch_bounds__(256)
fused_kernel(const float* __restrict__ xarg, float* __restrict__ xoutarg,
             const int* __restrict__ batch, const float* __restrict__ lw,
             float* __restrict__ Zbuf, int N) {
    constexpr int cm = FIRST ? 3 : 4;   // conv weight slot
    constexpr int lm = FIRST ? 1 : 2;   // lin weight slot
    __shared__ __align__(16) float Wc[D*WPAD];
    __shared__ __align__(16) float Wl[D*WPAD];
    __shared__ __align__(16) float W0[FIRST ? D*WPAD : 4];
    __shared__ float bc[D], bl[D], b0[FIRST ? D : 1];
    __shared__ __align__(16) float sSt[8][WPAD];    // per-warp staged input vector

    int t = threadIdx.x;
    for (int i = t; i < D*D; i += 256) {
        int col = i >> 5, k = i & 31;
        Wc[col*WPAD + k] = g_Wt[cm*D*D + i];
        Wl[col*WPAD + k] = g_Wt[lm*D*D + i];
        if (FIRST) W0[col*WPAD + k] = g_Wt[i];
    }
    if (t < D) {
        bc[t] = g_bf[cm*D + t];
        bl[t] = g_bf[lm*D + t];
        if (FIRST) b0[t] = g_bf[t];
    }
    __syncthreads();

    int w = t >> 5, lane = t & 31;
    int n0 = (blockIdx.x * 8 + w) * NPW;
    if (n0 >= N) return;
    int nend = n0 + NPW; if (nend > N) nend = N;

    const float* xin  = FIRST ? xarg : g_x1;
    float*       xout = FIRST ? g_x1 : xoutarg;
    float lw0 = FIRST ? lw[0] : 0.f;
    float lwl = lw[FIRST ? 1 : 2];

    const float NEGINF = __uint_as_float(0xff800000u);
    float z0max = NEGINF, z1max = NEGINF;
    int curseg = batch[n0];

    for (int node = n0; node < nend; node++) {
        int seg = batch[node];
        if (seg != curseg) {               // rare (batch sorted): flush maxes
            if (FIRST) atomicMax(&g_max[curseg*D + lane], fenc(z0max));
            atomicMax(&g_max[(FIRST ? 1 : 2)*GMAX*D + curseg*D + lane], fenc(z1max));
            z0max = NEGINF; z1max = NEGINF;
            curseg = seg;
        }

        float xself = xin[(size_t)node*D + lane];

        // ---- inline gather: acc = xself + sum of neighbor rows ----
        float acc = xself;
        {
            int rs = __ldg(&g_off[node]), re = __ldg(&g_off[node + 1]);
            int k = rs;
            for (; k + 8 <= re; k += 8) {
                int i0 = __ldg(&g_csr[k]),     i1 = __ldg(&g_csr[k + 1]);
                int i2 = __ldg(&g_csr[k + 2]), i3 = __ldg(&g_csr[k + 3]);
                int i4 = __ldg(&g_csr[k + 4]), i5 = __ldg(&g_csr[k + 5]);
                int i6 = __ldg(&g_csr[k + 6]), i7 = __ldg(&g_csr[k + 7]);
                float v0 = __ldg(&xin[(size_t)i0*D + lane]);
                float v1 = __ldg(&xin[(size_t)i1*D + lane]);
                float v2 = __ldg(&xin[(size_t)i2*D + lane]);
                float v3 = __ldg(&xin[(size_t)i3*D + lane]);
                float v4 = __ldg(&xin[(size_t)i4*D + lane]);
                float v5 = __ldg(&xin[(size_t)i5*D + lane]);
                float v6 = __ldg(&xin[(size_t)i6*D + lane]);
                float v7 = __ldg(&xin[(size_t)i7*D + lane]);
                acc += ((v0 + v1) + (v2 + v3)) + ((v4 + v5) + (v6 + v7));
            }
            for (; k < re; k++) acc += __ldg(&xin[(size_t)__ldg(&g_csr[k])*D + lane]);
        }

        // ---- optional layer-0 lin-MLP on raw x ----
        float Zval = 0.f;
        if (FIRST) {
            sSt[w][lane] = xself;
            __syncwarp();
            float h0;
            DOT32(h0, sSt[w], W0, b0);
            float z0 = elu1(h0);
            Zval = lw0 * z0;
            z0max = fmaxf(z0max, z0);      // layer0 max over RAW z0
            __syncwarp();
        }

        // ---- conv MLP: x' = ELU(BNfold(acc @ Wc)) ----
        sSt[w][lane] = acc;
        __syncwarp();
        float h1;
        DOT32(h1, sSt[w], Wc, bc);
        float xn = elu1(h1);
        xout[(size_t)node*D + lane] = xn;
        __syncwarp();

        // ---- lin MLP: z = lw * ELU(BNfold(x' @ Wl)) ----
        sSt[w][lane] = xn;
        __syncwarp();
        float h2;
        DOT32(h2, sSt[w], Wl, bl);
        float z = lwl * elu1(h2);

        if (FIRST) Zbuf[(size_t)node*D + lane] = Zval + z;
        else       Zbuf[(size_t)node*D + lane] += z;
        z1max = fmaxf(z1max, z);
    }

    // final flush (fenc(-inf) == init value, so this is always safe)
    if (FIRST) atomicMax(&g_max[curseg*D + lane], fenc(z0max));
    atomicMax(&g_max[(FIRST ? 1 : 2)*GMAX*D + curseg*D + lane], fenc(z1max));
}

// -------- out = sum of the three per-layer segment maxes --------
__global__ void final_kernel(float* __restrict__ out) {
    int i = blockIdx.x * blockDim.x + threadIdx.x;
    if (i < GMAX*D)
        out[i] = fdec(g_max[i]) + fdec(g_max[GMAX*D + i]) + fdec(g_max[2*GMAX*D + i]);
}

extern "C" void kernel_launch(void* const* d_in, const int* in_sizes, int n_in,
                              void* d_out, int out_size) {
    const float* x      = (const float*)d_in[0];
    const int*   ei     = (const int*)d_in[1];      // int32 (JAX x64 disabled)
    const int*   batch  = (const int*)d_in[2];
    const float* lw     = (const float*)d_in[3];
    const float* linW   = (const float*)d_in[4];
    const float* linb   = (const float*)d_in[5];
    const float* ling   = (const float*)d_in[6];
    const float* linbe  = (const float*)d_in[7];
    const float* linm   = (const float*)d_in[8];
    const float* linv   = (const float*)d_in[9];
    const float* convW  = (const float*)d_in[10];
    const float* convb  = (const float*)d_in[11];
    const float* convg  = (const float*)d_in[12];
    const float* convbe = (const float*)d_in[13];
    const float* convm  = (const float*)d_in[14];
    const float* convv  = (const float*)d_in[15];

    int N = in_sizes[0] / D;
    int E = in_sizes[1] / 2;
    int NB = (N + TILE - 1) / TILE;

    float* out = (float*)d_out;            // [G*D]
    float* Z   = out + GMAX * D;           // [N*D]
    float* xb  = Z + (size_t)N * D;        // [N*D] final x output

    int fused_blocks = (N + 8*NPW - 1) / (8*NPW);       // 64 nodes per block
    int e_blocks = (E + 255) / 256;
    int prep_n = N > 5*D*D ? N : 5*D*D;

    prep_kernel<<<(prep_n + 1023) / 1024, 1024>>>(linW, linb, ling, linbe, linm, linv,
                                                  convW, convb, convg, convbe, convm, convv, N);

    // CSR build (shared by both layers)
    hist_kernel<<<e_blocks, 256>>>(ei, E);
    tilesum_kernel<<<NB, 256>>>(N);
    tileoff_kernel<<<NB, TILE>>>(N, E, NB);
    fill_kernel<<<e_blocks, 256>>>(ei, E);

    // layer 1: fused gather + l0 + conv0 + lin1 (x -> g_x1)
    fused_kernel<true><<<fused_blocks, 256>>>(x, nullptr, batch, lw, Z, N);

    // layer 2: fused gather + conv1 + lin2 (g_x1 -> xb)
    fused_kernel<false><<<fused_blocks, 256>>>(nullptr, xb, batch, lw, Z, N);

    final_kernel<<<(GMAX*D + 255) / 256, 256>>>(out);
}